// round 4
// baseline (speedup 1.0000x reference)
#include <cuda_runtime.h>
#include <math.h>

#define Bn 2
#define Cn 64
#define CQn 8
#define Hn 270
#define Wn 480
#define HWn (Hn*Wn)
#define NPIX (Bn*HWn)
#define Hp 272   // padded H stride for transposed layouts

typedef unsigned long long ull;
__device__ __forceinline__ ull pk2(float lo, float hi){ ull r; asm("mov.b64 %0, {%1, %2};" : "=l"(r) : "f"(lo), "f"(hi)); return r; }
__device__ __forceinline__ void unpk2(ull v, float& lo, float& hi){ asm("mov.b64 {%0, %1}, %2;" : "=f"(lo), "=f"(hi) : "l"(v)); }
__device__ __forceinline__ void fma2(ull& d, ull a, ull b){ asm("fma.rn.f32x2 %0, %1, %2, %0;" : "+l"(d) : "l"(a), "l"(b)); }

// -------- scratch (device globals; allocation-free) --------
__device__ float g_q [Bn*CQn*HWn];        // [b][c8][h][w]
__device__ float g_k [Bn*CQn*HWn];
__device__ float g_v [Bn*Cn *HWn];        // [b][c][h][w]
__device__ float g_qT[Bn*Wn*CQn*Hp];      // [b][w][c8][h]
__device__ float g_kT[Bn*Wn*CQn*Hp];
__device__ float g_vT[Bn*Wn*Cn *Hp];      // [b][w][c][h]  (pad rows stay zero)
__device__ float g_ow [Bn*Cn*HWn];        // unnorm out_w
__device__ float g_ohT[Bn*Wn*Cn*Hp];      // unnorm out_h (transposed)
__device__ float g_sw [Bn*Hn*Wn];
__device__ float g_sh [Bn*Wn*Hn];
__device__ float g_inv[Bn*Hn*Wn];

// ================= K1: fused q/k/v projection (packed f32x2) =================
__global__ __launch_bounds__(256) void proj_kernel(
    const float* __restrict__ x,
    const float* __restrict__ Wq, const float* __restrict__ bq,
    const float* __restrict__ Wk, const float* __restrict__ bk,
    const float* __restrict__ Wv, const float* __restrict__ bv)
{
    __shared__ float Ws[80][65];
    __shared__ float bs[80];
    __shared__ float xs[64][64];
    int t = threadIdx.x;
    for (int i = t; i < 80*64; i += 256) {
        int o = i >> 6;
        float wv;
        if (o < 8)       wv = Wq[i];
        else if (o < 16) wv = Wk[i - 512];
        else             wv = Wv[i - 1024];
        Ws[o][i & 63] = wv;
    }
    if (t < 80) bs[t] = (t < 8) ? bq[t] : (t < 16 ? bk[t-8] : bv[t-16]);

    int p0 = blockIdx.x * 64;
    int b  = p0 / HWn;
    int r0 = p0 - b*HWn;
    const float* xb = x + (size_t)b*Cn*HWn + r0;
    for (int i = t; i < 64*64; i += 256) {
        int c = i >> 6, j = i & 63;
        xs[c][j] = xb[(size_t)c*HWn + j];
    }
    __syncthreads();

    int to = t >> 4;   // 16 groups of 5 output channels
    int tp = t & 15;   // 4 pixels (2 f32x2 pairs)
    ull acc2[5][2];
    #pragma unroll
    for (int i = 0; i < 5; i++) { acc2[i][0] = 0ull; acc2[i][1] = 0ull; }

    #pragma unroll 8
    for (int c = 0; c < 64; c++) {
        ulonglong2 xv = *(const ulonglong2*)&xs[c][tp*4];
        #pragma unroll
        for (int i = 0; i < 5; i++) {
            float wv = Ws[to*5+i][c];
            ull wb = pk2(wv, wv);
            fma2(acc2[i][0], wb, xv.x);
            fma2(acc2[i][1], wb, xv.y);
        }
    }
    int rr = r0 + tp*4;
    #pragma unroll
    for (int i = 0; i < 5; i++) {
        int o = to*5 + i;
        float bb = bs[o];
        float a0,a1,a2,a3;
        unpk2(acc2[i][0], a0, a1);
        unpk2(acc2[i][1], a2, a3);
        float4 res = make_float4(a0+bb, a1+bb, a2+bb, a3+bb);
        float* dst;
        if (o < 8)       dst = &g_q[(size_t)(b*CQn + o)*HWn + rr];
        else if (o < 16) dst = &g_k[(size_t)(b*CQn + o-8)*HWn + rr];
        else             dst = &g_v[(size_t)(b*Cn  + o-16)*HWn + rr];
        *(float4*)dst = res;
    }
}

// ================= K2: tiled transpose =================
__global__ __launch_bounds__(256) void transpose_kernel(int which, int nch)
{
    __shared__ float tile[32][33];
    const float* in; float* out;
    if (which == 0)      { in = g_q; out = g_qT; }
    else if (which == 1) { in = g_k; out = g_kT; }
    else                 { in = g_v; out = g_vT; }

    int bc = blockIdx.z;
    int b = bc / nch, ch = bc - b*nch;
    int w0 = blockIdx.x * 32, h0 = blockIdx.y * 32;
    int tx = threadIdx.x & 31, ty = threadIdx.x >> 5;

    const float* plane = in + (size_t)(b*nch + ch)*HWn;
    #pragma unroll
    for (int k2 = 0; k2 < 4; k2++) {
        int h = h0 + ty + 8*k2, w = w0 + tx;
        tile[ty+8*k2][tx] = (h < Hn) ? plane[h*Wn + w] : 0.f;
    }
    __syncthreads();
    #pragma unroll
    for (int k2 = 0; k2 < 4; k2++) {
        int w = w0 + ty + 8*k2, h = h0 + tx;
        if (h < Hn)
            out[((size_t)(b*Wn + w)*nch + ch)*Hp + h] = tile[tx][ty+8*k2];
    }
}

// shared-memory layout (floats) used by both attention kernels:
//  q_s  [8][96]   @ 0      (768)
//  k_s  [8][64]   @ 768    (512)
//  v_s  [64][68]  @ 1280   (4352)
//  dwt  [480]     @ 5632   (480)
//  p_s  [96][68]  @ 6112   (6528)   aliased by out_s[64][97]
#define SM_QS 0
#define SM_KS 768
#define SM_VS 1280
#define SM_DW 5632
#define SM_PS 6112
#define SMEM_FLOATS (6112 + 6528)
#define SMEM_BYTES  (SMEM_FLOATS*4)

// ================= K3: row attention (over width) =================
// grid (5, Hn, Bn), 96 threads. tile = 96 queries, 8 key chunks of 64.
__global__ __launch_bounds__(96) void row_attn_kernel(const float* __restrict__ dww)
{
    extern __shared__ float sm[];
    float* q_s = sm + SM_QS;
    float* k_s = sm + SM_KS;
    float* v_s = sm + SM_VS;
    float* dwt = sm + SM_DW;
    float* p_s = sm + SM_PS;
    float* out_s = sm + SM_PS;   // alias, pitch 97

    const int b = blockIdx.z, h = blockIdx.y, wt = blockIdx.x;
    const int t = threadIdx.x;
    const int qgroup = t >> 3, g = t & 7;
    const int q0 = qgroup * 8;
    const int wbase = wt * 96;

    for (int i = t; i < Wn; i += 96) dwt[i] = dww[i];
    #pragma unroll
    for (int c8 = 0; c8 < 8; c8++)
        q_s[c8*96 + t] = g_q[(size_t)(b*CQn+c8)*HWn + h*Wn + wbase + t];
    __syncthreads();

    ull qp[4][8];
    #pragma unroll
    for (int j = 0; j < 4; j++)
        #pragma unroll
        for (int c8 = 0; c8 < 8; c8++)
            qp[j][c8] = pk2(q_s[c8*96 + q0 + 2*j], q_s[c8*96 + q0 + 2*j + 1]);

    ull acc[8][8];
    #pragma unroll
    for (int qi = 0; qi < 8; qi++)
        #pragma unroll
        for (int cc = 0; cc < 8; cc++) acc[qi][cc] = 0ull;
    float ssum[8];
    #pragma unroll
    for (int qi = 0; qi < 8; qi++) ssum[qi] = 0.f;

    for (int ch = 0; ch < 8; ch++) {
        const int k0 = ch*64;
        for (int i = t; i < 512; i += 96) {
            int c8 = i >> 6, kl = i & 63;
            int kg = k0 + kl;
            k_s[c8*64 + kl] = (kg < Wn) ? g_k[(size_t)(b*CQn+c8)*HWn + h*Wn + kg] : 0.f;
        }
        for (int i = t; i < 1024; i += 96) {
            int c = i >> 4, kq = i & 15;
            int kg = k0 + kq*4;
            float4 val = make_float4(0.f,0.f,0.f,0.f);
            if (kg < Wn) val = *(const float4*)&g_v[(size_t)(b*Cn+c)*HWn + h*Wn + kg];
            *(float4*)&v_s[c*68 + kq*4] = val;
        }
        __syncthreads();

        // logits + exp for this thread's 8 queries x 8 keys
        #pragma unroll
        for (int jj = 0; jj < 8; jj++) {
            int kl = g + 8*jj;
            int kg = k0 + kl;
            ull lp[4] = {0ull,0ull,0ull,0ull};
            #pragma unroll
            for (int c8 = 0; c8 < 8; c8++) {
                float kv = k_s[c8*64 + kl];
                ull kb = pk2(kv, kv);
                fma2(lp[0], qp[0][c8], kb);
                fma2(lp[1], qp[1][c8], kb);
                fma2(lp[2], qp[2][c8], kb);
                fma2(lp[3], qp[3][c8], kb);
            }
            bool valid = (kg < Wn);
            #pragma unroll
            for (int j = 0; j < 4; j++) {
                float l0, l1; unpk2(lp[j], l0, l1);
                int qg0 = wbase + q0 + 2*j;
                int d0 = abs(qg0 - kg), d1 = abs(qg0 + 1 - kg);
                float p0v = valid ? __expf(l0 * dwt[d0]) : 0.f;
                float p1v = valid ? __expf(l1 * dwt[d1]) : 0.f;
                p_s[((2*j  )*12 + qgroup)*68 + kl] = p0v;
                p_s[((2*j+1)*12 + qgroup)*68 + kl] = p1v;
                ssum[2*j]   += p0v;
                ssum[2*j+1] += p1v;
            }
        }
        __syncthreads();

        // PV: acc[qi][cc] (f32x2 over key pairs)
        for (int vp4 = 0; vp4 < 16; vp4++) {
            ulonglong2 P[8];
            #pragma unroll
            for (int qi = 0; qi < 8; qi++)
                P[qi] = *(const ulonglong2*)&p_s[(qi*12 + qgroup)*68 + vp4*4];
            #pragma unroll
            for (int cc = 0; cc < 8; cc++) {
                ulonglong2 V = *(const ulonglong2*)&v_s[(cc*8+g)*68 + vp4*4];
                #pragma unroll
                for (int qi = 0; qi < 8; qi++) {
                    fma2(acc[qi][cc], P[qi].x, V.x);
                    fma2(acc[qi][cc], P[qi].y, V.y);
                }
            }
        }
        __syncthreads();
    }

    #pragma unroll
    for (int qi = 0; qi < 8; qi++) {
        float s = ssum[qi];
        s += __shfl_xor_sync(0xffffffffu, s, 1);
        s += __shfl_xor_sync(0xffffffffu, s, 2);
        s += __shfl_xor_sync(0xffffffffu, s, 4);
        if (g == 0) g_sw[(b*Hn + h)*Wn + wbase + q0 + qi] = s;
    }

    #pragma unroll
    for (int qi = 0; qi < 8; qi++)
        #pragma unroll
        for (int cc = 0; cc < 8; cc++) {
            float lo, hi; unpk2(acc[qi][cc], lo, hi);
            out_s[(cc*8+g)*97 + q0 + qi] = lo + hi;
        }
    __syncthreads();
    #pragma unroll 4
    for (int c = 0; c < 64; c++)
        g_ow[(size_t)(b*Cn + c)*HWn + h*Wn + wbase + t] = out_s[c*97 + t];
}

// ================= K4: column attention (over height), diag masked =================
// grid (3, Wn, Bn), 96 threads. tile = 96 queries (h), 5 key chunks of 64.
__global__ __launch_bounds__(96) void col_attn_kernel(const float* __restrict__ dwh)
{
    extern __shared__ float sm[];
    float* q_s = sm + SM_QS;
    float* k_s = sm + SM_KS;
    float* v_s = sm + SM_VS;
    float* dwt = sm + SM_DW;
    float* p_s = sm + SM_PS;
    float* out_s = sm + SM_PS;

    const int b = blockIdx.z, w = blockIdx.y, ht = blockIdx.x;
    const int t = threadIdx.x;
    const int qgroup = t >> 3, g = t & 7;
    const int q0 = qgroup * 8;
    const int hbase = ht * 96;

    for (int i = t; i < Hn; i += 96) dwt[i] = dwh[i];
    {
        int hg = hbase + t;
        #pragma unroll
        for (int c8 = 0; c8 < 8; c8++)
            q_s[c8*96 + t] = (hg < Hn) ? g_qT[((size_t)(b*Wn+w)*CQn + c8)*Hp + hg] : 0.f;
    }
    __syncthreads();

    ull qp[4][8];
    #pragma unroll
    for (int j = 0; j < 4; j++)
        #pragma unroll
        for (int c8 = 0; c8 < 8; c8++)
            qp[j][c8] = pk2(q_s[c8*96 + q0 + 2*j], q_s[c8*96 + q0 + 2*j + 1]);

    ull acc[8][8];
    #pragma unroll
    for (int qi = 0; qi < 8; qi++)
        #pragma unroll
        for (int cc = 0; cc < 8; cc++) acc[qi][cc] = 0ull;
    float ssum[8];
    #pragma unroll
    for (int qi = 0; qi < 8; qi++) ssum[qi] = 0.f;

    for (int ch = 0; ch < 5; ch++) {
        const int k0 = ch*64;
        for (int i = t; i < 512; i += 96) {
            int c8 = i >> 6, kl = i & 63;
            int kg = k0 + kl;
            k_s[c8*64 + kl] = (kg < Hn) ? g_kT[((size_t)(b*Wn+w)*CQn + c8)*Hp + kg] : 0.f;
        }
        for (int i = t; i < 1024; i += 96) {
            int c = i >> 4, kq = i & 15;
            int kg = k0 + kq*4;
            float4 val = make_float4(0.f,0.f,0.f,0.f);
            if (kg < Hn)  // pad rows [270,272) of g_vT are zero
                val = *(const float4*)&g_vT[((size_t)(b*Wn+w)*Cn + c)*Hp + kg];
            *(float4*)&v_s[c*68 + kq*4] = val;
        }
        __syncthreads();

        #pragma unroll
        for (int jj = 0; jj < 8; jj++) {
            int kl = g + 8*jj;
            int kg = k0 + kl;
            ull lp[4] = {0ull,0ull,0ull,0ull};
            #pragma unroll
            for (int c8 = 0; c8 < 8; c8++) {
                float kv = k_s[c8*64 + kl];
                ull kb = pk2(kv, kv);
                fma2(lp[0], qp[0][c8], kb);
                fma2(lp[1], qp[1][c8], kb);
                fma2(lp[2], qp[2][c8], kb);
                fma2(lp[3], qp[3][c8], kb);
            }
            bool valid = (kg < Hn);
            #pragma unroll
            for (int j = 0; j < 4; j++) {
                float l0, l1; unpk2(lp[j], l0, l1);
                int qg0 = hbase + q0 + 2*j;
                int d0 = abs(qg0 - kg);     if (d0 > Hn-1) d0 = Hn-1;
                int d1 = abs(qg0 + 1 - kg); if (d1 > Hn-1) d1 = Hn-1;
                float p0v = (valid && kg != qg0    ) ? __expf(l0 * dwt[d0]) : 0.f;
                float p1v = (valid && kg != qg0 + 1) ? __expf(l1 * dwt[d1]) : 0.f;
                p_s[((2*j  )*12 + qgroup)*68 + kl] = p0v;
                p_s[((2*j+1)*12 + qgroup)*68 + kl] = p1v;
                ssum[2*j]   += p0v;
                ssum[2*j+1] += p1v;
            }
        }
        __syncthreads();

        for (int vp4 = 0; vp4 < 16; vp4++) {
            ulonglong2 P[8];
            #pragma unroll
            for (int qi = 0; qi < 8; qi++)
                P[qi] = *(const ulonglong2*)&p_s[(qi*12 + qgroup)*68 + vp4*4];
            #pragma unroll
            for (int cc = 0; cc < 8; cc++) {
                ulonglong2 V = *(const ulonglong2*)&v_s[(cc*8+g)*68 + vp4*4];
                #pragma unroll
                for (int qi = 0; qi < 8; qi++) {
                    fma2(acc[qi][cc], P[qi].x, V.x);
                    fma2(acc[qi][cc], P[qi].y, V.y);
                }
            }
        }
        __syncthreads();
    }

    #pragma unroll
    for (int qi = 0; qi < 8; qi++) {
        float s = ssum[qi];
        s += __shfl_xor_sync(0xffffffffu, s, 1);
        s += __shfl_xor_sync(0xffffffffu, s, 2);
        s += __shfl_xor_sync(0xffffffffu, s, 4);
        int hq = hbase + q0 + qi;
        if (g == 0 && hq < Hn) g_sh[(b*Wn + w)*Hn + hq] = s;
    }

    #pragma unroll
    for (int qi = 0; qi < 8; qi++)
        #pragma unroll
        for (int cc = 0; cc < 8; cc++) {
            float lo, hi; unpk2(acc[qi][cc], lo, hi);
            out_s[(cc*8+g)*97 + q0 + qi] = lo + hi;
        }
    __syncthreads();
    {
        int hg = hbase + t;
        if (hg < Hn) {
            #pragma unroll 4
            for (int c = 0; c < 64; c++)
                g_ohT[((size_t)(b*Wn+w)*Cn + c)*Hp + hg] = out_s[c*97 + t];
        }
    }
}

// ================= K4.5: per-pixel 1/(s_h+s_w) =================
__global__ __launch_bounds__(256) void stats_kernel()
{
    int i = blockIdx.x*256 + threadIdx.x;
    if (i >= NPIX) return;
    int b = i / HWn, r = i - b*HWn;
    int h = r / Wn, w = r - h*Wn;
    float s = g_sw[i] + g_sh[(b*Wn + w)*Hn + h];
    g_inv[i] = 1.0f / s;
}

// ================= K5: combine + residual =================
__global__ __launch_bounds__(256) void combine_kernel(
    const float* __restrict__ x, const float* __restrict__ gamma_p,
    float* __restrict__ out)
{
    __shared__ float tile[32][33];
    int bc = blockIdx.z;
    int b = bc >> 6, c = bc & 63;
    int w0 = blockIdx.x * 32, h0 = blockIdx.y * 32;
    int tx = threadIdx.x & 31, ty = threadIdx.x >> 5;

    #pragma unroll
    for (int k2 = 0; k2 < 4; k2++) {
        int w = w0 + ty + 8*k2, h = h0 + tx;
        float v = 0.f;
        if (h < Hn) v = g_ohT[((size_t)(b*Wn+w)*Cn + c)*Hp + h];
        tile[ty+8*k2][tx] = v;
    }
    __syncthreads();
    float gamma = gamma_p[0];
    #pragma unroll
    for (int k2 = 0; k2 < 4; k2++) {
        int h = h0 + ty + 8*k2, w = w0 + tx;
        if (h >= Hn) continue;
        float oh = tile[tx][ty+8*k2];
        size_t idx = (size_t)(b*Cn + c)*HWn + h*Wn + w;
        float ow = g_ow[idx];
        float iv = g_inv[(b*Hn + h)*Wn + w];
        out[idx] = gamma * (oh + ow) * iv + x[idx];
    }
}

// ================= launch =================
extern "C" void kernel_launch(void* const* d_in, const int* in_sizes, int n_in,
                              void* d_out, int out_size)
{
    const float* x     = (const float*)d_in[0];
    const float* Wq    = (const float*)d_in[1];
    const float* bq    = (const float*)d_in[2];
    const float* Wk    = (const float*)d_in[3];
    const float* bk    = (const float*)d_in[4];
    const float* Wv    = (const float*)d_in[5];
    const float* bv    = (const float*)d_in[6];
    const float* gamma = (const float*)d_in[7];
    const float* dwh   = (const float*)d_in[8];
    const float* dww   = (const float*)d_in[9];
    float* out = (float*)d_out;

    cudaFuncSetAttribute(row_attn_kernel, cudaFuncAttributeMaxDynamicSharedMemorySize, SMEM_BYTES);
    cudaFuncSetAttribute(col_attn_kernel, cudaFuncAttributeMaxDynamicSharedMemorySize, SMEM_BYTES);

    proj_kernel<<<NPIX/64, 256>>>(x, Wq, bq, Wk, bk, Wv, bv);

    transpose_kernel<<<dim3(Wn/32, (Hn+31)/32, Bn*CQn), 256>>>(0, CQn);
    transpose_kernel<<<dim3(Wn/32, (Hn+31)/32, Bn*CQn), 256>>>(1, CQn);
    transpose_kernel<<<dim3(Wn/32, (Hn+31)/32, Bn*Cn ), 256>>>(2, Cn);

    row_attn_kernel<<<dim3(5, Hn, Bn), 96, SMEM_BYTES>>>(dww);
    col_attn_kernel<<<dim3(3, Wn, Bn), 96, SMEM_BYTES>>>(dwh);

    stats_kernel<<<(NPIX + 255)/256, 256>>>();

    combine_kernel<<<dim3(Wn/32, (Hn+31)/32, Bn*Cn), 256>>>(x, gamma, out);
}

// round 5
// speedup vs baseline: 1.3029x; 1.3029x over previous
#include <cuda_runtime.h>
#include <math.h>

#define Bn 2
#define Cn 64
#define CQn 8
#define Hn 270
#define Wn 480
#define HWn (Hn*Wn)
#define NPIX (Bn*HWn)
#define Hp 272   // padded H stride for transposed layouts

typedef unsigned long long ull;
__device__ __forceinline__ ull pk2(float lo, float hi){ ull r; asm("mov.b64 %0, {%1, %2};" : "=l"(r) : "f"(lo), "f"(hi)); return r; }
__device__ __forceinline__ void unpk2(ull v, float& lo, float& hi){ asm("mov.b64 {%0, %1}, %2;" : "=f"(lo), "=f"(hi) : "l"(v)); }
__device__ __forceinline__ void fma2(ull& d, ull a, ull b){ asm("fma.rn.f32x2 %0, %1, %2, %0;" : "+l"(d) : "l"(a), "l"(b)); }

// -------- scratch (device globals; allocation-free) --------
__device__ float g_q [Bn*CQn*HWn];        // [b][c8][h][w]
__device__ float g_k [Bn*CQn*HWn];
__device__ float g_v [Bn*Cn *HWn];        // [b][c][h][w]
__device__ float g_qT[Bn*Wn*CQn*Hp];      // [b][w][c8][h]
__device__ float g_kT[Bn*Wn*CQn*Hp];
__device__ float g_vT[Bn*Wn*Cn *Hp];      // [b][w][c][h]  (pad rows stay zero)
__device__ float g_ow [Bn*Cn*HWn];        // unnorm out_w
__device__ float g_ohT[Bn*Wn*Cn*Hp];      // unnorm out_h (transposed)
__device__ float g_sw [Bn*Hn*Wn];
__device__ float g_sh [Bn*Wn*Hn];
__device__ float g_inv[Bn*Hn*Wn];

// ================= K1: fused q/k/v projection (packed f32x2) =================
__global__ __launch_bounds__(256) void proj_kernel(
    const float* __restrict__ x,
    const float* __restrict__ Wq, const float* __restrict__ bq,
    const float* __restrict__ Wk, const float* __restrict__ bk,
    const float* __restrict__ Wv, const float* __restrict__ bv)
{
    __shared__ float Ws[80][65];
    __shared__ float bs[80];
    __shared__ __align__(16) float xs[64][64];
    int t = threadIdx.x;
    for (int i = t; i < 80*64; i += 256) {
        int o = i >> 6;
        float wv;
        if (o < 8)       wv = Wq[i];
        else if (o < 16) wv = Wk[i - 512];
        else             wv = Wv[i - 1024];
        Ws[o][i & 63] = wv;
    }
    if (t < 80) bs[t] = (t < 8) ? bq[t] : (t < 16 ? bk[t-8] : bv[t-16]);

    int p0 = blockIdx.x * 64;
    int b  = p0 / HWn;
    int r0 = p0 - b*HWn;
    const float* xb = x + (size_t)b*Cn*HWn + r0;
    for (int i = t; i < 64*64; i += 256) {
        int c = i >> 6, j = i & 63;
        xs[c][j] = xb[(size_t)c*HWn + j];
    }
    __syncthreads();

    int to = t >> 4;   // 16 groups of 5 output channels
    int tp = t & 15;   // 4 pixels (2 f32x2 pairs)
    ull acc2[5][2];
    #pragma unroll
    for (int i = 0; i < 5; i++) { acc2[i][0] = 0ull; acc2[i][1] = 0ull; }

    #pragma unroll 8
    for (int c = 0; c < 64; c++) {
        ulonglong2 xv = *(const ulonglong2*)&xs[c][tp*4];
        #pragma unroll
        for (int i = 0; i < 5; i++) {
            float wv = Ws[to*5+i][c];
            ull wb = pk2(wv, wv);
            fma2(acc2[i][0], wb, xv.x);
            fma2(acc2[i][1], wb, xv.y);
        }
    }
    int rr = r0 + tp*4;
    #pragma unroll
    for (int i = 0; i < 5; i++) {
        int o = to*5 + i;
        float bb = bs[o];
        float a0,a1,a2,a3;
        unpk2(acc2[i][0], a0, a1);
        unpk2(acc2[i][1], a2, a3);
        float4 res = make_float4(a0+bb, a1+bb, a2+bb, a3+bb);
        float* dst;
        if (o < 8)       dst = &g_q[(size_t)(b*CQn + o)*HWn + rr];
        else if (o < 16) dst = &g_k[(size_t)(b*CQn + o-8)*HWn + rr];
        else             dst = &g_v[(size_t)(b*Cn  + o-16)*HWn + rr];
        *(float4*)dst = res;
    }
}

// ================= K2: tiled transpose =================
__global__ __launch_bounds__(256) void transpose_kernel(int which, int nch)
{
    __shared__ float tile[32][33];
    const float* in; float* out;
    if (which == 0)      { in = g_q; out = g_qT; }
    else if (which == 1) { in = g_k; out = g_kT; }
    else                 { in = g_v; out = g_vT; }

    int bc = blockIdx.z;
    int b = bc / nch, ch = bc - b*nch;
    int w0 = blockIdx.x * 32, h0 = blockIdx.y * 32;
    int tx = threadIdx.x & 31, ty = threadIdx.x >> 5;

    const float* plane = in + (size_t)(b*nch + ch)*HWn;
    #pragma unroll
    for (int k2 = 0; k2 < 4; k2++) {
        int h = h0 + ty + 8*k2, w = w0 + tx;
        tile[ty+8*k2][tx] = (h < Hn) ? plane[h*Wn + w] : 0.f;
    }
    __syncthreads();
    #pragma unroll
    for (int k2 = 0; k2 < 4; k2++) {
        int w = w0 + ty + 8*k2, h = h0 + tx;
        if (h < Hn)
            out[((size_t)(b*Wn + w)*nch + ch)*Hp + h] = tile[tx][ty+8*k2];
    }
}

// ================= K3: row attention (over width) =================
// grid (8, Hn, Bn), 128 threads. tile = 64 queries, key chunks of 64.
// thread t: qgroup = t>>3 (16), g = t&7 (channel lane).
// thread owns queries q_local = qi*16+qgroup (qi=0..3), channels cc*8+g (cc=0..7).
__global__ __launch_bounds__(128) void row_attn_kernel(const float* __restrict__ dww)
{
    __shared__ __align__(16) float q_s[8*64];
    __shared__ __align__(16) float k_s[8*64];
    __shared__ __align__(16) float v_s[64*68];
    __shared__ __align__(16) float p_s[64*68];   // rows: qi*16+qgroup; aliased as out_s
    __shared__ float dwt[Wn];
    float* out_s = p_s;

    const int b = blockIdx.z, h = blockIdx.y, wt = blockIdx.x;
    const int t = threadIdx.x;
    const int qgroup = t >> 3, g = t & 7;
    const int wbase = wt * 64;

    for (int i = t; i < Wn; i += 128) dwt[i] = dww[i];
    for (int i = t; i < 512; i += 128) {
        int c8 = i >> 6, ql = i & 63;
        int wq = wbase + ql;
        q_s[c8*64 + ql] = (wq < Wn) ? g_q[(size_t)(b*CQn+c8)*HWn + h*Wn + wq] : 0.f;
    }
    __syncthreads();

    ull qp[2][8];
    #pragma unroll
    for (int j = 0; j < 2; j++)
        #pragma unroll
        for (int c8 = 0; c8 < 8; c8++)
            qp[j][c8] = pk2(q_s[c8*64 + (2*j  )*16 + qgroup],
                            q_s[c8*64 + (2*j+1)*16 + qgroup]);

    ull acc[4][8];
    #pragma unroll
    for (int qi = 0; qi < 4; qi++)
        #pragma unroll
        for (int cc = 0; cc < 8; cc++) acc[qi][cc] = 0ull;
    float ssum[4] = {0.f, 0.f, 0.f, 0.f};

    for (int ch = 0; ch < 8; ch++) {
        const int k0 = ch*64;
        for (int i = t; i < 512; i += 128) {
            int c8 = i >> 6, kl = i & 63;
            int kg = k0 + kl;
            k_s[c8*64 + kl] = (kg < Wn) ? g_k[(size_t)(b*CQn+c8)*HWn + h*Wn + kg] : 0.f;
        }
        for (int i = t; i < 1024; i += 128) {
            int c = i >> 4, kq = i & 15;
            int kg = k0 + kq*4;
            float4 val = make_float4(0.f,0.f,0.f,0.f);
            if (kg < Wn) val = *(const float4*)&g_v[(size_t)(b*Cn+c)*HWn + h*Wn + kg];
            *(float4*)&v_s[c*68 + kq*4] = val;
        }
        __syncthreads();

        // logits + exp: this thread's 4 queries x 8 keys
        #pragma unroll
        for (int jj = 0; jj < 8; jj++) {
            int kl = g + 8*jj;
            int kg = k0 + kl;
            ull lp0 = 0ull, lp1 = 0ull;
            #pragma unroll
            for (int c8 = 0; c8 < 8; c8++) {
                float kv = k_s[c8*64 + kl];
                ull kb = pk2(kv, kv);
                fma2(lp0, qp[0][c8], kb);
                fma2(lp1, qp[1][c8], kb);
            }
            bool valid = (kg < Wn);
            float l[4];
            unpk2(lp0, l[0], l[1]);
            unpk2(lp1, l[2], l[3]);
            #pragma unroll
            for (int qi = 0; qi < 4; qi++) {
                int wq = wbase + qi*16 + qgroup;
                int d = abs(wq - kg); if (d > Wn-1) d = Wn-1;
                float pv = valid ? __expf(l[qi] * dwt[d]) : 0.f;
                p_s[(qi*16 + qgroup)*68 + kl] = pv;
                ssum[qi] += pv;
            }
        }
        __syncthreads();

        // PV accumulate (f32x2 over key pairs)
        #pragma unroll 2
        for (int vp4 = 0; vp4 < 16; vp4++) {
            ulonglong2 P[4];
            #pragma unroll
            for (int qi = 0; qi < 4; qi++)
                P[qi] = *(const ulonglong2*)&p_s[(qi*16 + qgroup)*68 + vp4*4];
            #pragma unroll
            for (int cc = 0; cc < 8; cc++) {
                ulonglong2 V = *(const ulonglong2*)&v_s[(cc*8+g)*68 + vp4*4];
                #pragma unroll
                for (int qi = 0; qi < 4; qi++) {
                    fma2(acc[qi][cc], P[qi].x, V.x);
                    fma2(acc[qi][cc], P[qi].y, V.y);
                }
            }
        }
        __syncthreads();
    }

    #pragma unroll
    for (int qi = 0; qi < 4; qi++) {
        float s = ssum[qi];
        s += __shfl_xor_sync(0xffffffffu, s, 1);
        s += __shfl_xor_sync(0xffffffffu, s, 2);
        s += __shfl_xor_sync(0xffffffffu, s, 4);
        int wq = wbase + qi*16 + qgroup;
        if (g == 0 && wq < Wn) g_sw[(b*Hn + h)*Wn + wq] = s;
    }

    // stage outputs: out_s[channel][query] (conflict-free: bank = g*4+qgroup)
    #pragma unroll
    for (int qi = 0; qi < 4; qi++)
        #pragma unroll
        for (int cc = 0; cc < 8; cc++) {
            float lo, hi; unpk2(acc[qi][cc], lo, hi);
            out_s[(cc*8+g)*68 + qi*16 + qgroup] = lo + hi;
        }
    __syncthreads();
    {
        int tq = t & 63, half = t >> 6;
        int wq = wbase + tq;
        if (wq < Wn) {
            #pragma unroll 4
            for (int i = 0; i < 32; i++) {
                int c = half*32 + i;
                g_ow[(size_t)(b*Cn + c)*HWn + h*Wn + wq] = out_s[c*68 + tq];
            }
        }
    }
}

// ================= K4: column attention (over height), diag masked =================
// grid (5, Wn, Bn), 128 threads. tile = 64 queries (h), key chunks of 64.
__global__ __launch_bounds__(128) void col_attn_kernel(const float* __restrict__ dwh)
{
    __shared__ __align__(16) float q_s[8*64];
    __shared__ __align__(16) float k_s[8*64];
    __shared__ __align__(16) float v_s[64*68];
    __shared__ __align__(16) float p_s[64*68];
    __shared__ float dwt[Hn];
    float* out_s = p_s;

    const int b = blockIdx.z, w = blockIdx.y, ht = blockIdx.x;
    const int t = threadIdx.x;
    const int qgroup = t >> 3, g = t & 7;
    const int hbase = ht * 64;

    for (int i = t; i < Hn; i += 128) dwt[i] = dwh[i];
    for (int i = t; i < 512; i += 128) {
        int c8 = i >> 6, ql = i & 63;
        int hq = hbase + ql;
        q_s[c8*64 + ql] = (hq < Hn) ? g_qT[((size_t)(b*Wn+w)*CQn + c8)*Hp + hq] : 0.f;
    }
    __syncthreads();

    ull qp[2][8];
    #pragma unroll
    for (int j = 0; j < 2; j++)
        #pragma unroll
        for (int c8 = 0; c8 < 8; c8++)
            qp[j][c8] = pk2(q_s[c8*64 + (2*j  )*16 + qgroup],
                            q_s[c8*64 + (2*j+1)*16 + qgroup]);

    ull acc[4][8];
    #pragma unroll
    for (int qi = 0; qi < 4; qi++)
        #pragma unroll
        for (int cc = 0; cc < 8; cc++) acc[qi][cc] = 0ull;
    float ssum[4] = {0.f, 0.f, 0.f, 0.f};

    for (int ch = 0; ch < 5; ch++) {
        const int k0 = ch*64;
        for (int i = t; i < 512; i += 128) {
            int c8 = i >> 6, kl = i & 63;
            int kg = k0 + kl;
            k_s[c8*64 + kl] = (kg < Hn) ? g_kT[((size_t)(b*Wn+w)*CQn + c8)*Hp + kg] : 0.f;
        }
        for (int i = t; i < 1024; i += 128) {
            int c = i >> 4, kq = i & 15;
            int kg = k0 + kq*4;
            float4 val = make_float4(0.f,0.f,0.f,0.f);
            if (kg < Hn)  // pad rows [270,272) of g_vT are zero
                val = *(const float4*)&g_vT[((size_t)(b*Wn+w)*Cn + c)*Hp + kg];
            *(float4*)&v_s[c*68 + kq*4] = val;
        }
        __syncthreads();

        #pragma unroll
        for (int jj = 0; jj < 8; jj++) {
            int kl = g + 8*jj;
            int kg = k0 + kl;
            ull lp0 = 0ull, lp1 = 0ull;
            #pragma unroll
            for (int c8 = 0; c8 < 8; c8++) {
                float kv = k_s[c8*64 + kl];
                ull kb = pk2(kv, kv);
                fma2(lp0, qp[0][c8], kb);
                fma2(lp1, qp[1][c8], kb);
            }
            bool valid = (kg < Hn);
            float l[4];
            unpk2(lp0, l[0], l[1]);
            unpk2(lp1, l[2], l[3]);
            #pragma unroll
            for (int qi = 0; qi < 4; qi++) {
                int hq = hbase + qi*16 + qgroup;
                int d = abs(hq - kg); if (d > Hn-1) d = Hn-1;
                float pv = (valid && kg != hq) ? __expf(l[qi] * dwt[d]) : 0.f;
                p_s[(qi*16 + qgroup)*68 + kl] = pv;
                ssum[qi] += pv;
            }
        }
        __syncthreads();

        #pragma unroll 2
        for (int vp4 = 0; vp4 < 16; vp4++) {
            ulonglong2 P[4];
            #pragma unroll
            for (int qi = 0; qi < 4; qi++)
                P[qi] = *(const ulonglong2*)&p_s[(qi*16 + qgroup)*68 + vp4*4];
            #pragma unroll
            for (int cc = 0; cc < 8; cc++) {
                ulonglong2 V = *(const ulonglong2*)&v_s[(cc*8+g)*68 + vp4*4];
                #pragma unroll
                for (int qi = 0; qi < 4; qi++) {
                    fma2(acc[qi][cc], P[qi].x, V.x);
                    fma2(acc[qi][cc], P[qi].y, V.y);
                }
            }
        }
        __syncthreads();
    }

    #pragma unroll
    for (int qi = 0; qi < 4; qi++) {
        float s = ssum[qi];
        s += __shfl_xor_sync(0xffffffffu, s, 1);
        s += __shfl_xor_sync(0xffffffffu, s, 2);
        s += __shfl_xor_sync(0xffffffffu, s, 4);
        int hq = hbase + qi*16 + qgroup;
        if (g == 0 && hq < Hn) g_sh[(b*Wn + w)*Hn + hq] = s;
    }

    #pragma unroll
    for (int qi = 0; qi < 4; qi++)
        #pragma unroll
        for (int cc = 0; cc < 8; cc++) {
            float lo, hi; unpk2(acc[qi][cc], lo, hi);
            out_s[(cc*8+g)*68 + qi*16 + qgroup] = lo + hi;
        }
    __syncthreads();
    {
        int tq = t & 63, half = t >> 6;
        int hq = hbase + tq;
        if (hq < Hn) {
            #pragma unroll 4
            for (int i = 0; i < 32; i++) {
                int c = half*32 + i;
                g_ohT[((size_t)(b*Wn+w)*Cn + c)*Hp + hq] = out_s[c*68 + tq];
            }
        }
    }
}

// ================= K4.5: per-pixel 1/(s_h+s_w) =================
__global__ __launch_bounds__(256) void stats_kernel()
{
    int i = blockIdx.x*256 + threadIdx.x;
    if (i >= NPIX) return;
    int b = i / HWn, r = i - b*HWn;
    int h = r / Wn, w = r - h*Wn;
    float s = g_sw[i] + g_sh[(b*Wn + w)*Hn + h];
    g_inv[i] = 1.0f / s;
}

// ================= K5: combine + residual =================
__global__ __launch_bounds__(256) void combine_kernel(
    const float* __restrict__ x, const float* __restrict__ gamma_p,
    float* __restrict__ out)
{
    __shared__ float tile[32][33];
    int bc = blockIdx.z;
    int b = bc >> 6, c = bc & 63;
    int w0 = blockIdx.x * 32, h0 = blockIdx.y * 32;
    int tx = threadIdx.x & 31, ty = threadIdx.x >> 5;

    #pragma unroll
    for (int k2 = 0; k2 < 4; k2++) {
        int w = w0 + ty + 8*k2, h = h0 + tx;
        float v = 0.f;
        if (h < Hn) v = g_ohT[((size_t)(b*Wn+w)*Cn + c)*Hp + h];
        tile[ty+8*k2][tx] = v;
    }
    __syncthreads();
    float gamma = gamma_p[0];
    #pragma unroll
    for (int k2 = 0; k2 < 4; k2++) {
        int h = h0 + ty + 8*k2, w = w0 + tx;
        if (h >= Hn) continue;
        float oh = tile[tx][ty+8*k2];
        size_t idx = (size_t)(b*Cn + c)*HWn + h*Wn + w;
        float ow = g_ow[idx];
        float iv = g_inv[(b*Hn + h)*Wn + w];
        out[idx] = gamma * (oh + ow) * iv + x[idx];
    }
}

// ================= launch =================
extern "C" void kernel_launch(void* const* d_in, const int* in_sizes, int n_in,
                              void* d_out, int out_size)
{
    const float* x     = (const float*)d_in[0];
    const float* Wq    = (const float*)d_in[1];
    const float* bq    = (const float*)d_in[2];
    const float* Wk    = (const float*)d_in[3];
    const float* bk    = (const float*)d_in[4];
    const float* Wv    = (const float*)d_in[5];
    const float* bv    = (const float*)d_in[6];
    const float* gamma = (const float*)d_in[7];
    const float* dwh   = (const float*)d_in[8];
    const float* dww   = (const float*)d_in[9];
    float* out = (float*)d_out;

    proj_kernel<<<NPIX/64, 256>>>(x, Wq, bq, Wk, bk, Wv, bv);

    transpose_kernel<<<dim3(Wn/32, (Hn+31)/32, Bn*CQn), 256>>>(0, CQn);
    transpose_kernel<<<dim3(Wn/32, (Hn+31)/32, Bn*CQn), 256>>>(1, CQn);
    transpose_kernel<<<dim3(Wn/32, (Hn+31)/32, Bn*Cn ), 256>>>(2, Cn);

    row_attn_kernel<<<dim3(8, Hn, Bn), 128>>>(dww);
    col_attn_kernel<<<dim3(5, Wn, Bn), 128>>>(dwh);

    stats_kernel<<<(NPIX + 255)/256, 256>>>();

    combine_kernel<<<dim3(Wn/32, (Hn+31)/32, Bn*Cn), 256>>>(x, gamma, out);
}

// round 7
// speedup vs baseline: 2.9205x; 2.2415x over previous
#include <cuda_runtime.h>
#include <cuda_bf16.h>
#include <math.h>
#include <stdint.h>

#define Bn 2
#define Cn 64
#define CQn 8
#define Hn 270
#define Wn 480
#define HWn (Hn*Wn)
#define NPIX (Bn*HWn)
#define Hp 272   // padded H stride for transposed layouts

typedef unsigned long long ull;
__device__ __forceinline__ ull pk2(float lo, float hi){ ull r; asm("mov.b64 %0, {%1, %2};" : "=l"(r) : "f"(lo), "f"(hi)); return r; }
__device__ __forceinline__ void unpk2(ull v, float& lo, float& hi){ asm("mov.b64 {%0, %1}, %2;" : "=f"(lo), "=f"(hi) : "l"(v)); }
__device__ __forceinline__ void fma2(ull& d, ull a, ull b){ asm("fma.rn.f32x2 %0, %1, %2, %0;" : "+l"(d) : "l"(a), "l"(b)); }

__device__ __forceinline__ uint32_t tf32c(float f){
    uint32_t r; asm("cvt.rna.tf32.f32 %0, %1;" : "=r"(r) : "f"(f)); return r;
}
__device__ __forceinline__ uint32_t bfpack(float lo, float hi){
    __nv_bfloat162 b = __floats2bfloat162_rn(lo, hi);
    return *(uint32_t*)&b;
}
__device__ __forceinline__ void mma_tf32(float* c, const uint32_t* a, const uint32_t* b){
    asm volatile("mma.sync.aligned.m16n8k8.row.col.f32.tf32.tf32.f32 "
        "{%0,%1,%2,%3}, {%4,%5,%6,%7}, {%8,%9}, {%0,%1,%2,%3};"
        : "+f"(c[0]),"+f"(c[1]),"+f"(c[2]),"+f"(c[3])
        : "r"(a[0]),"r"(a[1]),"r"(a[2]),"r"(a[3]), "r"(b[0]),"r"(b[1]));
}
__device__ __forceinline__ void mma_bf16(float* c, const uint32_t* a, const uint32_t* b){
    asm volatile("mma.sync.aligned.m16n8k16.row.col.f32.bf16.bf16.f32 "
        "{%0,%1,%2,%3}, {%4,%5,%6,%7}, {%8,%9}, {%0,%1,%2,%3};"
        : "+f"(c[0]),"+f"(c[1]),"+f"(c[2]),"+f"(c[3])
        : "r"(a[0]),"r"(a[1]),"r"(a[2]),"r"(a[3]), "r"(b[0]),"r"(b[1]));
}

// -------- scratch (device globals; allocation-free) --------
__device__ float g_q [Bn*CQn*HWn];        // [b][c8][h][w]
__device__ float g_k [Bn*CQn*HWn];
__device__ float g_v [Bn*Cn *HWn];        // [b][c][h][w]
__device__ float g_qT[Bn*Wn*CQn*Hp];      // [b][w][c8][h]
__device__ float g_kT[Bn*Wn*CQn*Hp];
__device__ float g_vT[Bn*Wn*Cn *Hp];      // [b][w][c][h]  (pad rows stay zero)
__device__ float g_ow [Bn*Cn*HWn];        // unnorm out_w
__device__ float g_ohT[Bn*Wn*Cn*Hp];      // unnorm out_h (transposed)
__device__ float g_sw [Bn*Hn*Wn];
__device__ float g_sh [Bn*Wn*Hn];
__device__ float g_inv[Bn*Hn*Wn];

// ================= K1: fused q/k/v projection (packed f32x2) =================
__global__ __launch_bounds__(256) void proj_kernel(
    const float* __restrict__ x,
    const float* __restrict__ Wq, const float* __restrict__ bq,
    const float* __restrict__ Wk, const float* __restrict__ bk,
    const float* __restrict__ Wv, const float* __restrict__ bv)
{
    __shared__ float Ws[80][65];
    __shared__ float bs[80];
    __shared__ __align__(16) float xs[64][64];
    int t = threadIdx.x;
    for (int i = t; i < 80*64; i += 256) {
        int o = i >> 6;
        float wv;
        if (o < 8)       wv = Wq[i];
        else if (o < 16) wv = Wk[i - 512];
        else             wv = Wv[i - 1024];
        Ws[o][i & 63] = wv;
    }
    if (t < 80) bs[t] = (t < 8) ? bq[t] : (t < 16 ? bk[t-8] : bv[t-16]);

    int p0 = blockIdx.x * 64;
    int b  = p0 / HWn;
    int r0 = p0 - b*HWn;
    const float* xb = x + (size_t)b*Cn*HWn + r0;
    for (int i = t; i < 64*64; i += 256) {
        int c = i >> 6, j = i & 63;
        xs[c][j] = xb[(size_t)c*HWn + j];
    }
    __syncthreads();

    int to = t >> 4;
    int tp = t & 15;
    ull acc2[5][2];
    #pragma unroll
    for (int i = 0; i < 5; i++) { acc2[i][0] = 0ull; acc2[i][1] = 0ull; }

    #pragma unroll 8
    for (int c = 0; c < 64; c++) {
        ulonglong2 xv = *(const ulonglong2*)&xs[c][tp*4];
        #pragma unroll
        for (int i = 0; i < 5; i++) {
            float wv = Ws[to*5+i][c];
            ull wb = pk2(wv, wv);
            fma2(acc2[i][0], wb, xv.x);
            fma2(acc2[i][1], wb, xv.y);
        }
    }
    int rr = r0 + tp*4;
    #pragma unroll
    for (int i = 0; i < 5; i++) {
        int o = to*5 + i;
        float bb = bs[o];
        float a0,a1,a2,a3;
        unpk2(acc2[i][0], a0, a1);
        unpk2(acc2[i][1], a2, a3);
        float4 res = make_float4(a0+bb, a1+bb, a2+bb, a3+bb);
        float* dst;
        if (o < 8)       dst = &g_q[(size_t)(b*CQn + o)*HWn + rr];
        else if (o < 16) dst = &g_k[(size_t)(b*CQn + o-8)*HWn + rr];
        else             dst = &g_v[(size_t)(b*Cn  + o-16)*HWn + rr];
        *(float4*)dst = res;
    }
}

// ================= K2: tiled transpose =================
__global__ __launch_bounds__(256) void transpose_kernel(int which, int nch)
{
    __shared__ float tile[32][33];
    const float* in; float* out;
    if (which == 0)      { in = g_q; out = g_qT; }
    else if (which == 1) { in = g_k; out = g_kT; }
    else                 { in = g_v; out = g_vT; }

    int bc = blockIdx.z;
    int b = bc / nch, ch = bc - b*nch;
    int w0 = blockIdx.x * 32, h0 = blockIdx.y * 32;
    int tx = threadIdx.x & 31, ty = threadIdx.x >> 5;

    const float* plane = in + (size_t)(b*nch + ch)*HWn;
    #pragma unroll
    for (int k2 = 0; k2 < 4; k2++) {
        int h = h0 + ty + 8*k2, w = w0 + tx;
        tile[ty+8*k2][tx] = (h < Hn) ? plane[h*Wn + w] : 0.f;
    }
    __syncthreads();
    #pragma unroll
    for (int k2 = 0; k2 < 4; k2++) {
        int w = w0 + ty + 8*k2, h = h0 + tx;
        if (h < Hn)
            out[((size_t)(b*Wn + w)*nch + ch)*Hp + h] = tile[tx][ty+8*k2];
    }
}

// ================= K3: row attention via mma.sync =================
// 64 queries/block (4 warps x 16 rows), 64-key chunks. tf32 QK, bf16 PV.
__global__ __launch_bounds__(128) void row_attn_mma(const float* __restrict__ dww)
{
    __shared__ uint32_t q_s[8*72];              // tf32 [c8][q]
    __shared__ uint32_t k_s[8*72];              // tf32 [c8][key]
    __shared__ __align__(8) __nv_bfloat16 v_s[64*72];  // [c][key]
    __shared__ float out_s[64*68];
    __shared__ float dwt[Wn];

    const int b = blockIdx.z, h = blockIdx.y, wbase = blockIdx.x*64;
    const int t = threadIdx.x;
    const int w = t >> 5, lane = t & 31, gp = lane >> 2, tid4 = lane & 3;
    const int r0 = wbase + 16*w + gp, r1 = r0 + 8;   // this thread's query rows

    for (int i = t; i < Wn; i += 128) dwt[i] = dww[i];
    for (int i = t; i < 512; i += 128) {
        int c8 = i >> 6, ql = i & 63;
        int wq = wbase + ql;
        float v = (wq < Wn) ? g_q[(size_t)(b*CQn+c8)*HWn + h*Wn + wq] : 0.f;
        q_s[c8*72 + ql] = tf32c(v);
    }
    __syncthreads();

    uint32_t aq[4];
    aq[0] = q_s[tid4*72     + 16*w + gp];
    aq[1] = q_s[tid4*72     + 16*w + gp + 8];
    aq[2] = q_s[(tid4+4)*72 + 16*w + gp];
    aq[3] = q_s[(tid4+4)*72 + 16*w + gp + 8];

    float oc[8][4];
    #pragma unroll
    for (int j = 0; j < 8; j++) { oc[j][0]=oc[j][1]=oc[j][2]=oc[j][3]=0.f; }
    float s0 = 0.f, s1 = 0.f;

    for (int ch = 0; ch < 8; ch++) {
        const int k0 = ch*64;
        for (int i = t; i < 512; i += 128) {
            int c8 = i >> 6, kl = i & 63;
            int kg = k0 + kl;
            float v = (kg < Wn) ? g_k[(size_t)(b*CQn+c8)*HWn + h*Wn + kg] : 0.f;
            k_s[c8*72 + kl] = tf32c(v);
        }
        for (int i = t; i < 1024; i += 128) {
            int c = i >> 4, kq = i & 15;
            int kg = k0 + kq*4;
            float4 vv = make_float4(0.f,0.f,0.f,0.f);
            if (kg < Wn) vv = *(const float4*)&g_v[(size_t)(b*Cn+c)*HWn + h*Wn + kg];
            uint2 st = make_uint2(bfpack(vv.x, vv.y), bfpack(vv.z, vv.w));
            *(uint2*)&v_s[c*72 + kq*4] = st;
        }
        __syncthreads();

        // logits: 8 n8-tiles
        float ec[8][4];
        #pragma unroll
        for (int j = 0; j < 8; j++) {
            ec[j][0]=ec[j][1]=ec[j][2]=ec[j][3]=0.f;
            uint32_t bk[2];
            bk[0] = k_s[tid4*72     + 8*j + gp];
            bk[1] = k_s[(tid4+4)*72 + 8*j + gp];
            mma_tf32(ec[j], aq, bk);
        }

        const uint32_t* v32 = (const uint32_t*)v_s;
        #pragma unroll
        for (int kd = 0; kd < 4; kd++) {
            int kgA = k0 + 16*kd + 2*tid4;      // cols of tile 2kd
            int kgB = kgA + 8;                  // cols of tile 2kd+1
            float* eA = ec[2*kd];
            float* eB = ec[2*kd+1];
            int dA0 = abs(r0 - kgA);     if (dA0 > Wn-1) dA0 = Wn-1;
            int dA1 = abs(r0 - kgA - 1); if (dA1 > Wn-1) dA1 = Wn-1;
            int dA2 = abs(r1 - kgA);     if (dA2 > Wn-1) dA2 = Wn-1;
            int dA3 = abs(r1 - kgA - 1); if (dA3 > Wn-1) dA3 = Wn-1;
            int dB0 = abs(r0 - kgB);     if (dB0 > Wn-1) dB0 = Wn-1;
            int dB1 = abs(r0 - kgB - 1); if (dB1 > Wn-1) dB1 = Wn-1;
            int dB2 = abs(r1 - kgB);     if (dB2 > Wn-1) dB2 = Wn-1;
            int dB3 = abs(r1 - kgB - 1); if (dB3 > Wn-1) dB3 = Wn-1;
            float pA0 = (kgA   < Wn) ? __expf(eA[0]*dwt[dA0]) : 0.f;
            float pA1 = (kgA+1 < Wn) ? __expf(eA[1]*dwt[dA1]) : 0.f;
            float pA2 = (kgA   < Wn) ? __expf(eA[2]*dwt[dA2]) : 0.f;
            float pA3 = (kgA+1 < Wn) ? __expf(eA[3]*dwt[dA3]) : 0.f;
            float pB0 = (kgB   < Wn) ? __expf(eB[0]*dwt[dB0]) : 0.f;
            float pB1 = (kgB+1 < Wn) ? __expf(eB[1]*dwt[dB1]) : 0.f;
            float pB2 = (kgB   < Wn) ? __expf(eB[2]*dwt[dB2]) : 0.f;
            float pB3 = (kgB+1 < Wn) ? __expf(eB[3]*dwt[dB3]) : 0.f;
            s0 += pA0 + pA1 + pB0 + pB1;
            s1 += pA2 + pA3 + pB2 + pB3;

            uint32_t ap[4];
            ap[0] = bfpack(pA0, pA1);
            ap[1] = bfpack(pA2, pA3);
            ap[2] = bfpack(pB0, pB1);
            ap[3] = bfpack(pB2, pB3);

            #pragma unroll
            for (int jn = 0; jn < 8; jn++) {
                uint32_t bv[2];
                bv[0] = v32[(8*jn+gp)*36 + kd*8 + tid4];
                bv[1] = v32[(8*jn+gp)*36 + kd*8 + 4 + tid4];
                mma_bf16(oc[jn], ap, bv);
            }
        }
        __syncthreads();
    }

    // sum reduce over tid4 (lane bits 0,1)
    s0 += __shfl_xor_sync(0xffffffffu, s0, 1);
    s0 += __shfl_xor_sync(0xffffffffu, s0, 2);
    s1 += __shfl_xor_sync(0xffffffffu, s1, 1);
    s1 += __shfl_xor_sync(0xffffffffu, s1, 2);
    if (tid4 == 0) {
        if (r0 < Wn) g_sw[(b*Hn + h)*Wn + r0] = s0;
        if (r1 < Wn) g_sw[(b*Hn + h)*Wn + r1] = s1;
    }

    // stage out_s[c][q]
    #pragma unroll
    for (int jn = 0; jn < 8; jn++) {
        out_s[(8*jn+2*tid4  )*68 + 16*w + gp    ] = oc[jn][0];
        out_s[(8*jn+2*tid4+1)*68 + 16*w + gp    ] = oc[jn][1];
        out_s[(8*jn+2*tid4  )*68 + 16*w + gp + 8] = oc[jn][2];
        out_s[(8*jn+2*tid4+1)*68 + 16*w + gp + 8] = oc[jn][3];
    }
    __syncthreads();
    {
        int tq = t & 63, half = t >> 6;
        int wq = wbase + tq;
        if (wq < Wn) {
            #pragma unroll 4
            for (int i = 0; i < 32; i++) {
                int c = half*32 + i;
                g_ow[(size_t)(b*Cn + c)*HWn + h*Wn + wq] = out_s[c*68 + tq];
            }
        }
    }
}

// ================= K4: column attention via mma.sync (diag masked) =================
__global__ __launch_bounds__(128) void col_attn_mma(const float* __restrict__ dwh)
{
    __shared__ uint32_t q_s[8*72];
    __shared__ uint32_t k_s[8*72];
    __shared__ __align__(8) __nv_bfloat16 v_s[64*72];
    __shared__ float out_s[64*68];
    __shared__ float dwt[Hn];

    const int b = blockIdx.z, w = blockIdx.y, hbase = blockIdx.x*64;
    const int t = threadIdx.x;
    const int wp = t >> 5, lane = t & 31, gp = lane >> 2, tid4 = lane & 3;
    const int r0 = hbase + 16*wp + gp, r1 = r0 + 8;

    for (int i = t; i < Hn; i += 128) dwt[i] = dwh[i];
    for (int i = t; i < 512; i += 128) {
        int c8 = i >> 6, ql = i & 63;
        int hq = hbase + ql;
        float v = (hq < Hn) ? g_qT[((size_t)(b*Wn+w)*CQn + c8)*Hp + hq] : 0.f;
        q_s[c8*72 + ql] = tf32c(v);
    }
    __syncthreads();

    uint32_t aq[4];
    aq[0] = q_s[tid4*72     + 16*wp + gp];
    aq[1] = q_s[tid4*72     + 16*wp + gp + 8];
    aq[2] = q_s[(tid4+4)*72 + 16*wp + gp];
    aq[3] = q_s[(tid4+4)*72 + 16*wp + gp + 8];

    float oc[8][4];
    #pragma unroll
    for (int j = 0; j < 8; j++) { oc[j][0]=oc[j][1]=oc[j][2]=oc[j][3]=0.f; }
    float s0 = 0.f, s1 = 0.f;

    for (int ch = 0; ch < 5; ch++) {
        const int k0 = ch*64;
        for (int i = t; i < 512; i += 128) {
            int c8 = i >> 6, kl = i & 63;
            int kg = k0 + kl;
            float v = (kg < Hn) ? g_kT[((size_t)(b*Wn+w)*CQn + c8)*Hp + kg] : 0.f;
            k_s[c8*72 + kl] = tf32c(v);
        }
        for (int i = t; i < 1024; i += 128) {
            int c = i >> 4, kq = i & 15;
            int kg = k0 + kq*4;
            float4 vv = make_float4(0.f,0.f,0.f,0.f);
            if (kg < Hn)   // reads up to kg+3 <= 271 < Hp, pad rows zero
                vv = *(const float4*)&g_vT[((size_t)(b*Wn+w)*Cn + c)*Hp + kg];
            uint2 st = make_uint2(bfpack(vv.x, vv.y), bfpack(vv.z, vv.w));
            *(uint2*)&v_s[c*72 + kq*4] = st;
        }
        __syncthreads();

        float ec[8][4];
        #pragma unroll
        for (int j = 0; j < 8; j++) {
            ec[j][0]=ec[j][1]=ec[j][2]=ec[j][3]=0.f;
            uint32_t bk[2];
            bk[0] = k_s[tid4*72     + 8*j + gp];
            bk[1] = k_s[(tid4+4)*72 + 8*j + gp];
            mma_tf32(ec[j], aq, bk);
        }

        const uint32_t* v32 = (const uint32_t*)v_s;
        #pragma unroll
        for (int kd = 0; kd < 4; kd++) {
            int kgA = k0 + 16*kd + 2*tid4;
            int kgB = kgA + 8;
            float* eA = ec[2*kd];
            float* eB = ec[2*kd+1];
            int dA0 = abs(r0 - kgA);     if (dA0 > Hn-1) dA0 = Hn-1;
            int dA1 = abs(r0 - kgA - 1); if (dA1 > Hn-1) dA1 = Hn-1;
            int dA2 = abs(r1 - kgA);     if (dA2 > Hn-1) dA2 = Hn-1;
            int dA3 = abs(r1 - kgA - 1); if (dA3 > Hn-1) dA3 = Hn-1;
            int dB0 = abs(r0 - kgB);     if (dB0 > Hn-1) dB0 = Hn-1;
            int dB1 = abs(r0 - kgB - 1); if (dB1 > Hn-1) dB1 = Hn-1;
            int dB2 = abs(r1 - kgB);     if (dB2 > Hn-1) dB2 = Hn-1;
            int dB3 = abs(r1 - kgB - 1); if (dB3 > Hn-1) dB3 = Hn-1;
            float pA0 = (kgA   < Hn && kgA   != r0) ? __expf(eA[0]*dwt[dA0]) : 0.f;
            float pA1 = (kgA+1 < Hn && kgA+1 != r0) ? __expf(eA[1]*dwt[dA1]) : 0.f;
            float pA2 = (kgA   < Hn && kgA   != r1) ? __expf(eA[2]*dwt[dA2]) : 0.f;
            float pA3 = (kgA+1 < Hn && kgA+1 != r1) ? __expf(eA[3]*dwt[dA3]) : 0.f;
            float pB0 = (kgB   < Hn && kgB   != r0) ? __expf(eB[0]*dwt[dB0]) : 0.f;
            float pB1 = (kgB+1 < Hn && kgB+1 != r0) ? __expf(eB[1]*dwt[dB1]) : 0.f;
            float pB2 = (kgB   < Hn && kgB   != r1) ? __expf(eB[2]*dwt[dB2]) : 0.f;
            float pB3 = (kgB+1 < Hn && kgB+1 != r1) ? __expf(eB[3]*dwt[dB3]) : 0.f;
            s0 += pA0 + pA1 + pB0 + pB1;
            s1 += pA2 + pA3 + pB2 + pB3;

            uint32_t ap[4];
            ap[0] = bfpack(pA0, pA1);
            ap[1] = bfpack(pA2, pA3);
            ap[2] = bfpack(pB0, pB1);
            ap[3] = bfpack(pB2, pB3);

            #pragma unroll
            for (int jn = 0; jn < 8; jn++) {
                uint32_t bv[2];
                bv[0] = v32[(8*jn+gp)*36 + kd*8 + tid4];
                bv[1] = v32[(8*jn+gp)*36 + kd*8 + 4 + tid4];
                mma_bf16(oc[jn], ap, bv);
            }
        }
        __syncthreads();
    }

    s0 += __shfl_xor_sync(0xffffffffu, s0, 1);
    s0 += __shfl_xor_sync(0xffffffffu, s0, 2);
    s1 += __shfl_xor_sync(0xffffffffu, s1, 1);
    s1 += __shfl_xor_sync(0xffffffffu, s1, 2);
    if (tid4 == 0) {
        if (r0 < Hn) g_sh[(b*Wn + w)*Hn + r0] = s0;
        if (r1 < Hn) g_sh[(b*Wn + w)*Hn + r1] = s1;
    }

    #pragma unroll
    for (int jn = 0; jn < 8; jn++) {
        out_s[(8*jn+2*tid4  )*68 + 16*wp + gp    ] = oc[jn][0];
        out_s[(8*jn+2*tid4+1)*68 + 16*wp + gp    ] = oc[jn][1];
        out_s[(8*jn+2*tid4  )*68 + 16*wp + gp + 8] = oc[jn][2];
        out_s[(8*jn+2*tid4+1)*68 + 16*wp + gp + 8] = oc[jn][3];
    }
    __syncthreads();
    {
        int tq = t & 63, half = t >> 6;
        int hq = hbase + tq;
        if (hq < Hn) {
            #pragma unroll 4
            for (int i = 0; i < 32; i++) {
                int c = half*32 + i;
                g_ohT[((size_t)(b*Wn+w)*Cn + c)*Hp + hq] = out_s[c*68 + tq];
            }
        }
    }
}

// ================= K4.5: per-pixel 1/(s_h+s_w) =================
__global__ __launch_bounds__(256) void stats_kernel()
{
    int i = blockIdx.x*256 + threadIdx.x;
    if (i >= NPIX) return;
    int b = i / HWn, r = i - b*HWn;
    int h = r / Wn, w = r - h*Wn;
    float s = g_sw[i] + g_sh[(b*Wn + w)*Hn + h];
    g_inv[i] = 1.0f / s;
}

// ================= K5: combine + residual =================
__global__ __launch_bounds__(256) void combine_kernel(
    const float* __restrict__ x, const float* __restrict__ gamma_p,
    float* __restrict__ out)
{
    __shared__ float tile[32][33];
    int bc = blockIdx.z;
    int b = bc >> 6, c = bc & 63;
    int w0 = blockIdx.x * 32, h0 = blockIdx.y * 32;
    int tx = threadIdx.x & 31, ty = threadIdx.x >> 5;

    #pragma unroll
    for (int k2 = 0; k2 < 4; k2++) {
        int w = w0 + ty + 8*k2, h = h0 + tx;
        float v = 0.f;
        if (h < Hn) v = g_ohT[((size_t)(b*Wn+w)*Cn + c)*Hp + h];
        tile[ty+8*k2][tx] = v;
    }
    __syncthreads();
    float gamma = gamma_p[0];
    #pragma unroll
    for (int k2 = 0; k2 < 4; k2++) {
        int h = h0 + ty + 8*k2, w = w0 + tx;
        if (h >= Hn) continue;
        float oh = tile[tx][ty+8*k2];
        size_t idx = (size_t)(b*Cn + c)*HWn + h*Wn + w;
        float ow = g_ow[idx];
        float iv = g_inv[(b*Hn + h)*Wn + w];
        out[idx] = gamma * (oh + ow) * iv + x[idx];
    }
}

// ================= launch =================
extern "C" void kernel_launch(void* const* d_in, const int* in_sizes, int n_in,
                              void* d_out, int out_size)
{
    const float* x     = (const float*)d_in[0];
    const float* Wq    = (const float*)d_in[1];
    const float* bq    = (const float*)d_in[2];
    const float* Wk    = (const float*)d_in[3];
    const float* bk    = (const float*)d_in[4];
    const float* Wv    = (const float*)d_in[5];
    const float* bv    = (const float*)d_in[6];
    const float* gamma = (const float*)d_in[7];
    const float* dwh   = (const float*)d_in[8];
    const float* dww   = (const float*)d_in[9];
    float* out = (float*)d_out;

    proj_kernel<<<NPIX/64, 256>>>(x, Wq, bq, Wk, bk, Wv, bv);

    transpose_kernel<<<dim3(Wn/32, (Hn+31)/32, Bn*CQn), 256>>>(0, CQn);
    transpose_kernel<<<dim3(Wn/32, (Hn+31)/32, Bn*CQn), 256>>>(1, CQn);
    transpose_kernel<<<dim3(Wn/32, (Hn+31)/32, Bn*Cn ), 256>>>(2, Cn);

    row_attn_mma<<<dim3(8, Hn, Bn), 128>>>(dww);
    col_attn_mma<<<dim3(5, Wn, Bn), 128>>>(dwh);

    stats_kernel<<<(NPIX + 255)/256, 256>>>();

    combine_kernel<<<dim3(Wn/32, (Hn+31)/32, Bn*Cn), 256>>>(x, gamma, out);
}